// round 12
// baseline (speedup 1.0000x reference)
#include <cuda_runtime.h>
#include <cuda_bf16.h>
#include <math.h>

// ---------------- Problem constants ----------------
#define NN    512
#define LHIST 20
#define PLEN  10
#define HD    128      // H
#define ED    64       // E
#define NHEAD 10
#define FFD   2048
#define DD    130      // D = H+2
#define DP    144      // padded D (multiple of 16)
#define DHD   13       // D / NH
#define NLAY  3
#define GRID  264      // persistent blocks: 2 per SM on 132 SMs
#define NT    256      // threads per block

// ---------------- Device state ----------------
__device__ float g_Wcomb[4*HD*4];
__device__ float g_bcomb[4*HD];
__device__ float g_x[NN*DP];
__device__ float g_Sh[NN*HD];
__device__ float g_c[NN*HD];
__device__ float g_gates[NN*4*HD];
__device__ float g_qkv[NN*3*DD];
__device__ float g_att[NN*DP];
__device__ float g_tmp[NN*DP];
__device__ float g_ff1[NN*FFD];
__device__ float g_part[8*NN*DP];
__device__ float g_mlp1[NN*HD];
__device__ float g_mlp2[NN*HD];
__device__ float g_inp[NN*4];
// Repacked weights (K 130 -> 144)
__device__ float g_qkvP[NLAY*3*DD*DP];
__device__ float g_outP[NLAY*DD*DP];
__device__ float g_ff1P[NLAY*FFD*DP];
__device__ float g_spP[HD*DP];
// Fused gate weights: Wf = W_hh @ W_sp (512 x 144), bspW = W_hh @ b_sp
__device__ float g_Wf[4*HD*DP];
__device__ float g_bspW[4*HD];
// Grid barrier (simple, proven) + per-M-group tile counters for epilogue fusion
__device__ volatile unsigned g_gen;
__device__ unsigned g_cnt;
__device__ unsigned g_tileCnt[16];

__device__ __forceinline__ float sigm(float x){ return 1.f/(1.f+expf(-x)); }

// ---------------- Grid-wide barrier (simple, R6-proven) ----------------
__device__ __forceinline__ void gridbar() {
    __syncthreads();
    if (threadIdx.x == 0) {
        unsigned old = g_gen;
        __threadfence();
        if (atomicAdd(&g_cnt, 1u) == GRID - 1) {
            g_cnt = 0;
            __threadfence();
            g_gen = old + 1;
        } else {
            while (g_gen == old) { __nanosleep(32); }
        }
        __threadfence();
    }
    __syncthreads();
}

// ---------------- Tiled GEMM with optional last-finisher epilogue ----------------
// C = A(512 x K) @ B(N x K)^T. TMv in {32,64} x TN=64 tile, 256 threads,
// double-buffered, K multiple of 16. flags: 1=relu, 2=add resid.
// splitK>1: write partials (no bias) at z*NN*ldc.
// EPI: 0=none, 1=LayerNorm over this M-group's rows (x = LN(x [+eBias] + sum_p eAdd)),
//      2=LSTM pointwise for this M-group's tokens.
// The last tile-finisher of each M-group (counter need) runs the epilogue.
template<int TMv, int EPI>
__device__ void dgemm_t(const float* __restrict__ A, const float* __restrict__ B,
                        const float* __restrict__ bias, const float* __restrict__ resid,
                        float* __restrict__ C, int N, int lda, int ldb, int ldc,
                        int K, int splitK, int flags, float* sm,
                        int need = 0,
                        const float* eAdd = nullptr, int eP = 0,
                        const float* eBias = nullptr,
                        const float* eS = nullptr, const float* eB = nullptr,
                        const float* eInp = nullptr, int eIstride = 0)
{
    const int MR = TMv/16;                    // rows per thread (4 or 2)
    const int tilesM = NN/TMv;
    int tilesN = (N + 63) >> 6;
    int total = tilesM * tilesN * splitK;
    int kLen = K / splitK;
    int nCh = kLen >> 4;
    const int SST = 68;
    const int SBUF = 16*SST;
    float* As = sm;
    float* Bs = sm + 2*SBUF;
    int tid = threadIdx.x;
    int lrow = tid >> 2, lk4 = (tid & 3) * 4;
    int tx = (tid & 15) * 4, ty = (tid >> 4) * MR;
    bool aload = (TMv == 64) || (tid < 128);
    __shared__ unsigned s_last;

    for (int u = blockIdx.x; u < total; u += GRID) {
        int z  = u / (tilesM * tilesN);
        int r  = u - z * (tilesM * tilesN);
        int bm = (r / tilesN) * TMv, bn = (r % tilesN) * 64;
        int kS = z * kLen;
        const float* Ab = A + (size_t)(bm + lrow) * lda + kS + lk4;
        int gn = bn + lrow;
        const float* Bb = B + (size_t)gn * ldb + kS + lk4;
        bool bok = gn < N;

        float4 pa = make_float4(0.f,0.f,0.f,0.f), pb;
        if (aload) pa = *(const float4*)Ab;
        pb = bok ? *(const float4*)Bb : make_float4(0.f,0.f,0.f,0.f);
        if (aload) {
            As[(lk4+0)*SST+lrow]=pa.x; As[(lk4+1)*SST+lrow]=pa.y;
            As[(lk4+2)*SST+lrow]=pa.z; As[(lk4+3)*SST+lrow]=pa.w;
        }
        Bs[(lk4+0)*SST+lrow]=pb.x; Bs[(lk4+1)*SST+lrow]=pb.y;
        Bs[(lk4+2)*SST+lrow]=pb.z; Bs[(lk4+3)*SST+lrow]=pb.w;
        __syncthreads();

        float acc[MR][4];
        #pragma unroll
        for (int i = 0; i < MR; i++)
            #pragma unroll
            for (int jj = 0; jj < 4; jj++) acc[i][jj] = 0.f;

        for (int c = 0; c < nCh; c++) {
            int cur = (c & 1) * SBUF;
            if (c + 1 < nCh) {
                if (aload) pa = *(const float4*)(Ab + (c+1)*16);
                pb = bok ? *(const float4*)(Bb + (c+1)*16) : make_float4(0.f,0.f,0.f,0.f);
            }
            #pragma unroll
            for (int kk = 0; kk < 16; kk++) {
                float4 bv = *(const float4*)&Bs[cur + kk*SST + tx];
                float av[MR];
                if (MR == 4) {
                    float4 t = *(const float4*)&As[cur + kk*SST + ty];
                    av[0]=t.x; av[1]=t.y; av[2]=t.z; av[3]=t.w;
                } else {
                    float2 t = *(const float2*)&As[cur + kk*SST + ty];
                    av[0]=t.x; av[1]=t.y;
                }
                #pragma unroll
                for (int i = 0; i < MR; i++) {
                    acc[i][0]+=av[i]*bv.x; acc[i][1]+=av[i]*bv.y;
                    acc[i][2]+=av[i]*bv.z; acc[i][3]+=av[i]*bv.w;
                }
            }
            if (c + 1 < nCh) {
                int nb = ((c+1) & 1) * SBUF;
                if (aload) {
                    As[nb+(lk4+0)*SST+lrow]=pa.x; As[nb+(lk4+1)*SST+lrow]=pa.y;
                    As[nb+(lk4+2)*SST+lrow]=pa.z; As[nb+(lk4+3)*SST+lrow]=pa.w;
                }
                Bs[nb+(lk4+0)*SST+lrow]=pb.x; Bs[nb+(lk4+1)*SST+lrow]=pb.y;
                Bs[nb+(lk4+2)*SST+lrow]=pb.z; Bs[nb+(lk4+3)*SST+lrow]=pb.w;
            }
            __syncthreads();
        }

        size_t zoff = (splitK > 1) ? (size_t)z * NN * ldc : 0;
        #pragma unroll
        for (int i = 0; i < MR; i++) {
            int m = bm + ty + i;
            #pragma unroll
            for (int jj = 0; jj < 4; jj++) {
                int n = bn + tx + jj;
                if (n >= N) continue;
                float v = acc[i][jj];
                if (bias)      v += bias[n];
                if (flags & 1) v = fmaxf(v, 0.f);
                if (flags & 2) v += resid[(size_t)m*ldc + n];
                C[zoff + (size_t)m*ldc + n] = v;
            }
        }

        if (EPI != 0) {
            __threadfence();                       // publish this tile's stores
            __syncthreads();                       // all threads done storing
            if (tid == 0) {
                int ci = bm >> 5;
                unsigned oldv = atomicAdd(&g_tileCnt[ci], 1u);
                unsigned isl = (oldv == (unsigned)(need - 1)) ? 1u : 0u;
                if (isl) atomicExch(&g_tileCnt[ci], 0u);
                s_last = isl;
            }
            __syncthreads();
            if (s_last) {
                __threadfence();                   // acquire: see all tiles of group
                if (EPI == 1) {
                    // LayerNorm rows [bm, bm+TMv): x = LN(x [+eBias] + sum_p eAdd)
                    int lane = tid & 31;
                    for (int rr = tid >> 5; rr < TMv; rr += 8) {
                        int w = bm + rr;
                        float v[5];
                        float s1 = 0.f, s2 = 0.f;
                        #pragma unroll
                        for (int i = 0; i < 5; i++) {
                            int idx = lane + i*32;
                            float xv = 0.f;
                            if (idx < DD) {
                                xv = g_x[w*DP + idx];
                                if (eBias) xv += eBias[idx];
                                for (int p = 0; p < eP; p++)
                                    xv += eAdd[(size_t)p*NN*DP + w*DP + idx];
                            }
                            v[i] = xv; s1 += xv; s2 += xv*xv;
                        }
                        #pragma unroll
                        for (int o = 16; o; o >>= 1) {
                            s1 += __shfl_xor_sync(0xffffffffu, s1, o);
                            s2 += __shfl_xor_sync(0xffffffffu, s2, o);
                        }
                        float mean = s1 * (1.f/DD);
                        float var  = s2 * (1.f/DD) - mean*mean;
                        float rstd = rsqrtf(var + 1e-5f);
                        #pragma unroll
                        for (int i = 0; i < 5; i++) {
                            int idx = lane + i*32;
                            if (idx < DD)
                                g_x[w*DP + idx] = (v[i] - mean)*rstd*eS[idx] + eB[idx];
                        }
                    }
                } else {
                    // LSTM pointwise for tokens [bm, bm+TMv)   (TMv == 32 here)
                    for (int e = tid; e < TMv*HD; e += NT) {
                        int n = bm + (e >> 7), j = e & 127;
                        float in0 = eInp[n*eIstride+0], in1 = eInp[n*eIstride+1];
                        float in2 = eInp[n*eIstride+2], in3 = eInp[n*eIstride+3];
                        float g[4];
                        #pragma unroll
                        for (int gi = 0; gi < 4; gi++) {
                            int row = gi*HD + j;
                            g[gi] = g_gates[n*(4*HD) + row] + g_bcomb[row]
                                  + g_Wcomb[row*4+0]*in0 + g_Wcomb[row*4+1]*in1
                                  + g_Wcomb[row*4+2]*in2 + g_Wcomb[row*4+3]*in3;
                        }
                        int ce = n*HD + j;
                        float c2 = sigm(g[1])*g_c[ce] + sigm(g[0])*tanhf(g[2]);
                        g_c[ce] = c2;
                        g_x[n*DP + j] = sigm(g[3])*tanhf(c2);
                        if (j < 2) g_x[n*DP + HD + j] = (j == 0) ? in0 : in1;
                    }
                }
            }
        }
        __syncthreads();
    }
}

// ---------------- Attention phase: KV in smem, 8 partials/token, 160 units ----------------
#define ATT_SK (NN*DHD + 4)
__device__ void dattn(float* sm) {
    float* sK = sm;
    float* sV = sm + ATT_SK;
    int tid = threadIdx.x;
    for (int u = blockIdx.x; u < NHEAD*16; u += GRID) {
        int h = u >> 4, chunk = u & 15;
        int bq = h*DHD, bk = DD + h*DHD, bv = 2*DD + h*DHD;
        for (int idx = tid; idx < NN*DHD; idx += NT) {
            int m = idx / DHD, c = idx - m*DHD;
            int sa = idx + (m >> 7);
            sK[sa] = g_qkv[m*3*DD + bk + c];
            sV[sa] = g_qkv[m*3*DD + bv + c];
        }
        __syncthreads();

        int token = chunk*32 + (tid >> 3);
        int p = tid & 7;
        const float scale = rsqrtf((float)DHD);
        float q[DHD];
        #pragma unroll
        for (int c = 0; c < DHD; c++) q[c] = g_qkv[token*3*DD + bq + c] * scale;

        float mx = -1e30f, l = 0.f, acc[DHD];
        #pragma unroll
        for (int c = 0; c < DHD; c++) acc[c] = 0.f;
        int mbase = p * 64;
        for (int i = 0; i < 64; i++) {
            int m = mbase + i;
            const float* kr = &sK[m*DHD + (m >> 7)];
            const float* vr = &sV[m*DHD + (m >> 7)];
            float s = q[0]*kr[0];
            #pragma unroll
            for (int c = 1; c < DHD; c++) s += q[c]*kr[c];
            if (s <= mx) {
                float e = __expf(s - mx);
                l += e;
                #pragma unroll
                for (int c = 0; c < DHD; c++) acc[c] += e*vr[c];
            } else {
                float corr = __expf(mx - s);
                l = l*corr + 1.f;
                #pragma unroll
                for (int c = 0; c < DHD; c++) acc[c] = acc[c]*corr + vr[c];
                mx = s;
            }
        }
        #pragma unroll
        for (int off = 1; off < 8; off <<= 1) {
            float om = __shfl_xor_sync(0xffffffffu, mx, off);
            float ol = __shfl_xor_sync(0xffffffffu, l, off);
            float nm = fmaxf(mx, om);
            float c1 = __expf(mx - nm), c2 = __expf(om - nm);
            l = l*c1 + ol*c2;
            #pragma unroll
            for (int c = 0; c < DHD; c++) {
                float oa = __shfl_xor_sync(0xffffffffu, acc[c], off);
                acc[c] = acc[c]*c1 + oa*c2;
            }
            mx = nm;
        }
        if (p == 0) {
            float rl = 1.f / l;
            #pragma unroll
            for (int c = 0; c < DHD; c++) g_att[token*DP + bq + c] = acc[c]*rl;
        }
        __syncthreads();
    }
}

// ---------------- LSTM pointwise (standalone, for the zero-gates init step) ----------------
__device__ void dlstm_pt(const float* __restrict__ inp, int istride) {
    for (int e = blockIdx.x*NT + threadIdx.x; e < NN*HD; e += GRID*NT) {
        int n = e >> 7, j = e & 127;
        float in0 = inp[n*istride+0], in1 = inp[n*istride+1];
        float in2 = inp[n*istride+2], in3 = inp[n*istride+3];
        float g[4];
        #pragma unroll
        for (int gi = 0; gi < 4; gi++) {
            int row = gi*HD + j;
            g[gi] = g_gates[n*(4*HD) + row] + g_bcomb[row]
                  + g_Wcomb[row*4+0]*in0 + g_Wcomb[row*4+1]*in1
                  + g_Wcomb[row*4+2]*in2 + g_Wcomb[row*4+3]*in3;
        }
        float c2 = sigm(g[1])*g_c[e] + sigm(g[0])*tanhf(g[2]);
        g_c[e] = c2;
        g_x[n*DP + j] = sigm(g[3])*tanhf(c2);
        if (j < 2) g_x[n*DP + HD + j] = (j == 0) ? in0 : in1;
    }
}

// ---------------- Rollout head ----------------
__device__ void dhead(const float* __restrict__ W_pl, const float* __restrict__ b_pl,
                      const float* __restrict__ cf, int cfs, float* __restrict__ outp)
{
    int n = blockIdx.x*NT + threadIdx.x;
    if (n >= NN) return;
    const float* xr = g_mlp2 + n*HD;
    float a0 = b_pl[0], a1 = b_pl[1];
    #pragma unroll 4
    for (int k = 0; k < HD; k++) {
        a0 += xr[k]*W_pl[k];
        a1 += xr[k]*W_pl[HD+k];
    }
    const float* c = cf + n*cfs;
    const float DT = 0.1f;
    float v0 = a0*DT + c[2], v1 = a1*DT + c[3];
    float p0 = a0*(DT*DT*0.5f) + v0*DT + c[0];
    float p1 = a1*(DT*DT*0.5f) + v1*DT + c[1];
    outp[n*(PLEN*4)+0] = p0; outp[n*(PLEN*4)+1] = p1;
    outp[n*(PLEN*4)+2] = v0; outp[n*(PLEN*4)+3] = v1;
    g_inp[n*4+0] = p0; g_inp[n*4+1] = p1; g_inp[n*4+2] = v0; g_inp[n*4+3] = v1;
}

// ---------------- Setup phase 1 ----------------
#define RP_ROWS (NLAY*3*DD + NLAY*DD + NLAY*FFD + HD)
__device__ void dsetup(const float* W_ih, const float* W_emb, const float* b_emb,
                       const float* b_ih, const float* b_hh,
                       const float* qkv_w, const float* out_w,
                       const float* ff1_w, const float* W_sp)
{
    int gtid = blockIdx.x*NT + threadIdx.x;
    const int nthr = GRID*NT;
    for (int j = gtid; j < 4*HD; j += nthr) {
        float wc0=0.f, wc1=0.f, wc2=0.f, wc3=0.f;
        float bb = b_ih[j] + b_hh[j];
        #pragma unroll 8
        for (int e = 0; e < ED; e++) {
            float w = W_ih[j*ED + e];
            bb  += w * b_emb[e];
            wc0 += w * W_emb[e*4 + 0];
            wc1 += w * W_emb[e*4 + 1];
            wc2 += w * W_emb[e*4 + 2];
            wc3 += w * W_emb[e*4 + 3];
        }
        g_Wcomb[j*4+0]=wc0; g_Wcomb[j*4+1]=wc1; g_Wcomb[j*4+2]=wc2; g_Wcomb[j*4+3]=wc3;
        g_bcomb[j]=bb;
    }
    for (int i = gtid; i < NN*HD; i += nthr) g_c[i] = 0.f;
    for (int i = gtid; i < NN*4*HD; i += nthr) g_gates[i] = 0.f;
    for (int i = gtid; i < NN*DP; i += nthr) { g_x[i] = 0.f; g_att[i] = 0.f; }
    for (int idx = gtid; idx < RP_ROWS*DP; idx += nthr) {
        int row = idx / DP, k = idx - row*DP;
        const float* src; float* dst; int r;
        if (row < NLAY*3*DD)                         { src = qkv_w; dst = g_qkvP; r = row; }
        else if (row < NLAY*3*DD+NLAY*DD)            { src = out_w; dst = g_outP; r = row - NLAY*3*DD; }
        else if (row < NLAY*3*DD+NLAY*DD+NLAY*FFD)   { src = ff1_w; dst = g_ff1P; r = row - NLAY*3*DD - NLAY*DD; }
        else                                         { src = W_sp;  dst = g_spP;  r = row - NLAY*3*DD - NLAY*DD - NLAY*FFD; }
        dst[r*DP + k] = (k < DD) ? src[r*DD + k] : 0.f;
    }
}

// ---------------- Setup phase 2: Wf = W_hh @ spP, bspW = W_hh @ b_sp ----------------
__device__ void dsetup2(const float* W_hh, const float* b_sp)
{
    int gtid = blockIdx.x*NT + threadIdx.x;
    const int nthr = GRID*NT;
    for (int idx = gtid; idx < 4*HD*DP; idx += nthr) {
        int row = idx / DP, d = idx - row*DP;
        float s = 0.f;
        #pragma unroll 8
        for (int r = 0; r < HD; r++) s += W_hh[row*HD + r] * g_spP[r*DP + d];
        g_Wf[idx] = s;
    }
    for (int row = gtid; row < 4*HD; row += nthr) {
        float s = 0.f;
        #pragma unroll 8
        for (int r = 0; r < HD; r++) s += W_hh[row*HD + r] * b_sp[r];
        g_bspW[row] = s;
    }
}

// ---------------- Encoder stack: 5 barriers per layer ----------------
__device__ void dsp(const float* qkv_b, const float* out_b, const float* ff1_b,
                    const float* ff2_w, const float* ff2_b,
                    const float* ln1_s, const float* ln1_b,
                    const float* ln2_s, const float* ln2_b,
                    const float* b_sp, bool emitSh, float* sm)
{
    for (int j = 0; j < NLAY; j++) {
        dgemm_t<32,0>(g_x, g_qkvP + (size_t)j*3*DD*DP, qkv_b + j*3*DD, nullptr, g_qkv,
                      3*DD, DP, DP, 3*DD, DP, 1, 0, sm);
        gridbar();
        dattn(sm);
        gridbar();
        // out-proj + LN1 fused (need = 3 N-tiles per 32-row group)
        dgemm_t<32,1>(g_att, g_outP + (size_t)j*DD*DP, out_b + j*DD, nullptr, g_tmp,
                      DD, DP, DP, DP, DP, 1, 0, sm,
                      3, g_tmp, 1, nullptr, ln1_s + j*DD, ln1_b + j*DD);
        gridbar();
        dgemm_t<64,0>(g_x, g_ff1P + (size_t)j*FFD*DP, ff1_b + j*FFD, nullptr, g_ff1,
                      FFD, DP, DP, FFD, DP, 1, 1, sm);
        gridbar();
        // ff2 (splitK=8) + LN2 fused (need = 3 N-tiles * 8 z per 64-row group)
        dgemm_t<64,1>(g_ff1, ff2_w + (size_t)j*DD*FFD, nullptr, nullptr, g_part,
                      DD, FFD, FFD, DP, FFD, 8, 0, sm,
                      24, g_part, 8, ff2_b + j*DD, ln2_s + j*DD, ln2_b + j*DD);
        gridbar();
    }
    if (emitSh) {
        dgemm_t<32,0>(g_x, g_spP, b_sp, nullptr, g_Sh, HD, DP, DP, HD, DP, 1, 0, sm);
        gridbar();
    }
}

// ---------------- Megakernel ----------------
__global__ void __launch_bounds__(NT, 2) mega(
    const float* Tracks, const float* W_emb, const float* b_emb,
    const float* W_ih, const float* W_hh, const float* b_ih, const float* b_hh,
    const float* qkv_w, const float* qkv_b, const float* out_w, const float* out_b,
    const float* ff1_w, const float* ff1_b, const float* ff2_w, const float* ff2_b,
    const float* ln1_s, const float* ln1_b, const float* ln2_s, const float* ln2_b,
    const float* W_sp, const float* b_sp, const float* W_p1, const float* b_p1,
    const float* W_p2, const float* b_p2, const float* W_pl, const float* b_pl,
    float* out)
{
    extern __shared__ float sm[];
    dsetup(W_ih, W_emb, b_emb, b_ih, b_hh, qkv_w, out_w, ff1_w, W_sp);
    gridbar();
    dsetup2(W_hh, b_sp);
    gridbar();

    // History: t=-1 uses Tracks[:,0,1:] with zero carry (g_gates zeroed in setup)
    for (int t = -1; t < LHIST; t++) {
        const float* ib = (t < 0) ? (Tracks + 1) : (Tracks + t*5 + 1);
        if (t >= 0) {
            // gates = x_prev @ Wf^T + W_hh@b_sp, LSTM pointwise fused as epilogue
            // (need = 8 N-tiles per 32-token group)
            dgemm_t<32,2>(g_x, g_Wf, g_bspW, nullptr, g_gates,
                          4*HD, DP, DP, 4*HD, DP, 1, 0, sm,
                          8, nullptr, 0, nullptr, nullptr, nullptr, ib, LHIST*5);
            gridbar();
        } else {
            dlstm_pt(ib, LHIST*5);
            gridbar();
        }
        dsp(qkv_b, out_b, ff1_b, ff2_w, ff2_b, ln1_s, ln1_b, ln2_s, ln2_b, b_sp,
            /*emitSh=*/(t == LHIST-1), sm);
    }
    // Rollout
    for (int t = 0; t < PLEN; t++) {
        dgemm_t<32,0>(g_Sh, W_p1, b_p1, g_Sh, g_mlp1, HD, HD, HD, HD, HD, 1, 3, sm);
        gridbar();
        dgemm_t<32,0>(g_mlp1, W_p2, b_p2, g_mlp1, g_mlp2, HD, HD, HD, HD, HD, 1, 3, sm);
        gridbar();
        dhead(W_pl, b_pl, (t == 0) ? (Tracks + (LHIST-1)*5 + 1) : g_inp,
              (t == 0) ? LHIST*5 : 4, out + t*4);
        gridbar();
        if (t < PLEN - 1) {     // last rm_sp's carry is discarded by the scan
            dgemm_t<32,2>(g_x, g_Wf, g_bspW, nullptr, g_gates,
                          4*HD, DP, DP, 4*HD, DP, 1, 0, sm,
                          8, nullptr, 0, nullptr, nullptr, nullptr, g_inp, 4);
            gridbar();
            dsp(qkv_b, out_b, ff1_b, ff2_w, ff2_b, ln1_s, ln1_b, ln2_s, ln2_b, b_sp,
                /*emitSh=*/true, sm);
        }
    }
}

// ---------------- Host ----------------
extern "C" void kernel_launch(void* const* d_in, const int* in_sizes, int n_in,
                              void* d_out, int out_size) {
    const float* Tracks = (const float*)d_in[0];
    const float* W_emb  = (const float*)d_in[1];
    const float* b_emb  = (const float*)d_in[2];
    const float* W_ih   = (const float*)d_in[3];
    const float* W_hh   = (const float*)d_in[4];
    const float* b_ih   = (const float*)d_in[5];
    const float* b_hh   = (const float*)d_in[6];
    const float* qkv_w  = (const float*)d_in[7];
    const float* qkv_b  = (const float*)d_in[8];
    const float* out_w  = (const float*)d_in[9];
    const float* out_b  = (const float*)d_in[10];
    const float* ff1_w  = (const float*)d_in[11];
    const float* ff1_b  = (const float*)d_in[12];
    const float* ff2_w  = (const float*)d_in[13];
    const float* ff2_b  = (const float*)d_in[14];
    const float* ln1_s  = (const float*)d_in[15];
    const float* ln1_b  = (const float*)d_in[16];
    const float* ln2_s  = (const float*)d_in[17];
    const float* ln2_b  = (const float*)d_in[18];
    const float* W_sp   = (const float*)d_in[19];
    const float* b_sp   = (const float*)d_in[20];
    const float* W_p1   = (const float*)d_in[21];
    const float* b_p1   = (const float*)d_in[22];
    const float* W_p2   = (const float*)d_in[23];
    const float* b_p2   = (const float*)d_in[24];
    const float* W_pl   = (const float*)d_in[25];
    const float* b_pl   = (const float*)d_in[26];
    float* out = (float*)d_out;

    // smem = max(attention KV: 2*(512*13+4)*4 = 53280B, gemm: 4*16*68*4 = 17408B)
    const int SMEM = 2*ATT_SK*(int)sizeof(float);
    static int configured = 0;
    if (!configured) {
        cudaFuncSetAttribute(mega, cudaFuncAttributeMaxDynamicSharedMemorySize, SMEM);
        configured = 1;
    }

    mega<<<GRID, NT, SMEM>>>(Tracks, W_emb, b_emb, W_ih, W_hh, b_ih, b_hh,
                             qkv_w, qkv_b, out_w, out_b, ff1_w, ff1_b, ff2_w, ff2_b,
                             ln1_s, ln1_b, ln2_s, ln2_b, W_sp, b_sp,
                             W_p1, b_p1, W_p2, b_p2, W_pl, b_pl, out);
}

// round 15
// speedup vs baseline: 1.1533x; 1.1533x over previous
#include <cuda_runtime.h>
#include <cuda_bf16.h>
#include <math.h>

// ---------------- Problem constants ----------------
#define NN    512
#define LHIST 20
#define PLEN  10
#define HD    128      // H
#define ED    64       // E
#define NHEAD 10
#define FFD   2048
#define DD    130      // D = H+2
#define DP    144      // padded D (multiple of 16)
#define DHD   13       // D / NH
#define NLAY  3
#define GRID  264      // persistent blocks: 2 per SM on 132 SMs
#define NT    256      // threads per block

// ---------------- Device state ----------------
__device__ float g_Wcomb[4*HD*4];
__device__ float g_bcomb[4*HD];
__device__ float g_x[NN*DP];
__device__ float g_c[NN*HD];
__device__ float g_gates[NN*4*HD];
__device__ float g_qkv[NN*3*DD];
__device__ float g_att[NN*DP];
__device__ float g_tmp[NN*DP];
__device__ float g_ff1[NN*FFD];
__device__ float g_part[8*NN*DP];
__device__ float g_inp[NN*4];
// Repacked weights (K 130 -> 144)
__device__ float g_qkvP[NLAY*3*DD*DP];
__device__ float g_outP[NLAY*DD*DP];
__device__ float g_ff1P[NLAY*FFD*DP];
__device__ float g_spP[HD*DP];
// Fused gate weights: Wf = W_hh @ W_sp (512 x 144), bspW = W_hh @ b_sp
__device__ float g_Wf[4*HD*DP];
__device__ float g_bspW[4*HD];
// Grid barrier (simple, R6-proven)
__device__ volatile unsigned g_gen;
__device__ unsigned g_cnt;

__device__ __forceinline__ float sigm(float x){ return 1.f/(1.f+expf(-x)); }

// ---------------- Grid-wide barrier (R6-proven, with nanosleep wakeup) ----------------
__device__ __forceinline__ void gridbar() {
    __syncthreads();
    if (threadIdx.x == 0) {
        unsigned old = g_gen;
        __threadfence();
        if (atomicAdd(&g_cnt, 1u) == GRID - 1) {
            g_cnt = 0;
            __threadfence();
            g_gen = old + 1;
        } else {
            while (g_gen == old) { __nanosleep(32); }
        }
        __threadfence();
    }
    __syncthreads();
}

// ---------------- Tiled GEMM phase (R6-proven, UNTOUCHED) ----------------
// C = A(512 x K) @ B(N x K)^T. TMv in {32,64} x TN=64 tile, 256 threads,
// double-buffered, K multiple of 16. flags: 1=relu, 2=add resid.
// splitK>1: write partials (no bias) at z*NN*ldc.
template<int TMv>
__device__ void dgemm_t(const float* __restrict__ A, const float* __restrict__ B,
                        const float* __restrict__ bias, const float* __restrict__ resid,
                        float* __restrict__ C, int N, int lda, int ldb, int ldc,
                        int K, int splitK, int flags, float* sm)
{
    const int MR = TMv/16;                    // rows per thread (4 or 2)
    const int tilesM = NN/TMv;
    int tilesN = (N + 63) >> 6;
    int total = tilesM * tilesN * splitK;
    int kLen = K / splitK;
    int nCh = kLen >> 4;
    const int SST = 68;
    const int SBUF = 16*SST;
    float* As = sm;
    float* Bs = sm + 2*SBUF;
    int tid = threadIdx.x;
    int lrow = tid >> 2, lk4 = (tid & 3) * 4;
    int tx = (tid & 15) * 4, ty = (tid >> 4) * MR;
    bool aload = (TMv == 64) || (tid < 128);

    for (int u = blockIdx.x; u < total; u += GRID) {
        int z  = u / (tilesM * tilesN);
        int r  = u - z * (tilesM * tilesN);
        int bm = (r / tilesN) * TMv, bn = (r % tilesN) * 64;
        int kS = z * kLen;
        const float* Ab = A + (size_t)(bm + lrow) * lda + kS + lk4;
        int gn = bn + lrow;
        const float* Bb = B + (size_t)gn * ldb + kS + lk4;
        bool bok = gn < N;

        float4 pa = make_float4(0.f,0.f,0.f,0.f), pb;
        if (aload) pa = *(const float4*)Ab;
        pb = bok ? *(const float4*)Bb : make_float4(0.f,0.f,0.f,0.f);
        if (aload) {
            As[(lk4+0)*SST+lrow]=pa.x; As[(lk4+1)*SST+lrow]=pa.y;
            As[(lk4+2)*SST+lrow]=pa.z; As[(lk4+3)*SST+lrow]=pa.w;
        }
        Bs[(lk4+0)*SST+lrow]=pb.x; Bs[(lk4+1)*SST+lrow]=pb.y;
        Bs[(lk4+2)*SST+lrow]=pb.z; Bs[(lk4+3)*SST+lrow]=pb.w;
        __syncthreads();

        float acc[MR][4];
        #pragma unroll
        for (int i = 0; i < MR; i++)
            #pragma unroll
            for (int jj = 0; jj < 4; jj++) acc[i][jj] = 0.f;

        for (int c = 0; c < nCh; c++) {
            int cur = (c & 1) * SBUF;
            if (c + 1 < nCh) {
                if (aload) pa = *(const float4*)(Ab + (c+1)*16);
                pb = bok ? *(const float4*)(Bb + (c+1)*16) : make_float4(0.f,0.f,0.f,0.f);
            }
            #pragma unroll
            for (int kk = 0; kk < 16; kk++) {
                float4 bv = *(const float4*)&Bs[cur + kk*SST + tx];
                float av[MR];
                if (MR == 4) {
                    float4 t = *(const float4*)&As[cur + kk*SST + ty];
                    av[0]=t.x; av[1]=t.y; av[2]=t.z; av[3]=t.w;
                } else {
                    float2 t = *(const float2*)&As[cur + kk*SST + ty];
                    av[0]=t.x; av[1]=t.y;
                }
                #pragma unroll
                for (int i = 0; i < MR; i++) {
                    acc[i][0]+=av[i]*bv.x; acc[i][1]+=av[i]*bv.y;
                    acc[i][2]+=av[i]*bv.z; acc[i][3]+=av[i]*bv.w;
                }
            }
            if (c + 1 < nCh) {
                int nb = ((c+1) & 1) * SBUF;
                if (aload) {
                    As[nb+(lk4+0)*SST+lrow]=pa.x; As[nb+(lk4+1)*SST+lrow]=pa.y;
                    As[nb+(lk4+2)*SST+lrow]=pa.z; As[nb+(lk4+3)*SST+lrow]=pa.w;
                }
                Bs[nb+(lk4+0)*SST+lrow]=pb.x; Bs[nb+(lk4+1)*SST+lrow]=pb.y;
                Bs[nb+(lk4+2)*SST+lrow]=pb.z; Bs[nb+(lk4+3)*SST+lrow]=pb.w;
            }
            __syncthreads();
        }

        size_t zoff = (splitK > 1) ? (size_t)z * NN * ldc : 0;
        #pragma unroll
        for (int i = 0; i < MR; i++) {
            int m = bm + ty + i;
            #pragma unroll
            for (int jj = 0; jj < 4; jj++) {
                int n = bn + tx + jj;
                if (n >= N) continue;
                float v = acc[i][jj];
                if (bias)      v += bias[n];
                if (flags & 1) v = fmaxf(v, 0.f);
                if (flags & 2) v += resid[(size_t)m*ldc + n];
                C[zoff + (size_t)m*ldc + n] = v;
            }
        }
        __syncthreads();
    }
}

// ---------------- Attention phase: KV in smem, 8 partials/token, 160 units ----------------
#define ATT_SK (NN*DHD + 4)
__device__ void dattn(float* sm) {
    float* sK = sm;
    float* sV = sm + ATT_SK;
    int tid = threadIdx.x;
    for (int u = blockIdx.x; u < NHEAD*16; u += GRID) {
        int h = u >> 4, chunk = u & 15;
        int bq = h*DHD, bk = DD + h*DHD, bv = 2*DD + h*DHD;
        for (int idx = tid; idx < NN*DHD; idx += NT) {
            int m = idx / DHD, c = idx - m*DHD;
            int sa = idx + (m >> 7);
            sK[sa] = g_qkv[m*3*DD + bk + c];
            sV[sa] = g_qkv[m*3*DD + bv + c];
        }
        __syncthreads();

        int token = chunk*32 + (tid >> 3);
        int p = tid & 7;
        const float scale = rsqrtf((float)DHD);
        float q[DHD];
        #pragma unroll
        for (int c = 0; c < DHD; c++) q[c] = g_qkv[token*3*DD + bq + c] * scale;

        float mx = -1e30f, l = 0.f, acc[DHD];
        #pragma unroll
        for (int c = 0; c < DHD; c++) acc[c] = 0.f;
        int mbase = p * 64;
        for (int i = 0; i < 64; i++) {
            int m = mbase + i;
            const float* kr = &sK[m*DHD + (m >> 7)];
            const float* vr = &sV[m*DHD + (m >> 7)];
            float s = q[0]*kr[0];
            #pragma unroll
            for (int c = 1; c < DHD; c++) s += q[c]*kr[c];
            if (s <= mx) {
                float e = __expf(s - mx);
                l += e;
                #pragma unroll
                for (int c = 0; c < DHD; c++) acc[c] += e*vr[c];
            } else {
                float corr = __expf(mx - s);
                l = l*corr + 1.f;
                #pragma unroll
                for (int c = 0; c < DHD; c++) acc[c] = acc[c]*corr + vr[c];
                mx = s;
            }
        }
        #pragma unroll
        for (int off = 1; off < 8; off <<= 1) {
            float om = __shfl_xor_sync(0xffffffffu, mx, off);
            float ol = __shfl_xor_sync(0xffffffffu, l, off);
            float nm = fmaxf(mx, om);
            float c1 = __expf(mx - nm), c2 = __expf(om - nm);
            l = l*c1 + ol*c2;
            #pragma unroll
            for (int c = 0; c < DHD; c++) {
                float oa = __shfl_xor_sync(0xffffffffu, acc[c], off);
                acc[c] = acc[c]*c1 + oa*c2;
            }
            mx = nm;
        }
        if (p == 0) {
            float rl = 1.f / l;
            #pragma unroll
            for (int c = 0; c < DHD; c++) g_att[token*DP + bq + c] = acc[c]*rl;
        }
        __syncthreads();
    }
}

// ---------------- LayerNorm phase ----------------
__device__ void dln(const float* __restrict__ add, int P, const float* __restrict__ bias,
                    const float* __restrict__ s, const float* __restrict__ b)
{
    int w = blockIdx.x * (NT/32) + (threadIdx.x >> 5);
    int lane = threadIdx.x & 31;
    if (w >= NN) return;
    float v[5];
    float s1 = 0.f, s2 = 0.f;
    #pragma unroll
    for (int i = 0; i < 5; i++) {
        int idx = lane + i*32;
        float xv = 0.f;
        if (idx < DD) {
            xv = g_x[w*DP + idx];
            if (bias) xv += bias[idx];
            for (int p = 0; p < P; p++) xv += add[(size_t)p*NN*DP + w*DP + idx];
        }
        v[i] = xv; s1 += xv; s2 += xv*xv;
    }
    #pragma unroll
    for (int o = 16; o; o >>= 1) {
        s1 += __shfl_xor_sync(0xffffffffu, s1, o);
        s2 += __shfl_xor_sync(0xffffffffu, s2, o);
    }
    float mean = s1 * (1.f/DD);
    float var  = s2 * (1.f/DD) - mean*mean;
    float rstd = rsqrtf(var + 1e-5f);
    #pragma unroll
    for (int i = 0; i < 5; i++) {
        int idx = lane + i*32;
        if (idx < DD) g_x[w*DP + idx] = (v[i] - mean)*rstd*s[idx] + b[idx];
    }
}

// ---------------- LSTM pointwise (after fused gates GEMM) ----------------
__device__ void dlstm_pt(const float* __restrict__ inp, int istride) {
    for (int e = blockIdx.x*NT + threadIdx.x; e < NN*HD; e += GRID*NT) {
        int n = e >> 7, j = e & 127;
        float in0 = inp[n*istride+0], in1 = inp[n*istride+1];
        float in2 = inp[n*istride+2], in3 = inp[n*istride+3];
        float g[4];
        #pragma unroll
        for (int gi = 0; gi < 4; gi++) {
            int row = gi*HD + j;
            g[gi] = g_gates[n*(4*HD) + row] + g_bcomb[row]
                  + g_Wcomb[row*4+0]*in0 + g_Wcomb[row*4+1]*in1
                  + g_Wcomb[row*4+2]*in2 + g_Wcomb[row*4+3]*in3;
        }
        float c2 = sigm(g[1])*g_c[e] + sigm(g[0])*tanhf(g[2]);
        g_c[e] = c2;
        g_x[n*DP + j] = sigm(g[3])*tanhf(c2);
        if (j < 2) g_x[n*DP + HD + j] = (j == 0) ? in0 : in1;
    }
}

// ---------------- Fused rollout phase: Sh -> mlp1 -> mlp2 -> head, row-independent ----
// 16 blocks, block rg handles rows [rg*32, rg*32+32). No intermediate gmem, 1 barrier.
#define XS 148                        // stage stride for x (36 float4s + pad)
#define WS 132                        // stride for W chunks and 32x128 tiles
// mini-GEMM: Out[32xWS] = act( Asrc[32 x asst](:,0:K) @ Wsrc[128 x ldw]^T + bias ) [+ Asrc resid]
__device__ __forceinline__ void mini_gemm(
    const float* As_, int asst, const float* __restrict__ Wsrc, int ldw,
    const float* __restrict__ bias, int relu, int resid,
    float* Out, int K, float* Wb, int tid)
{
    int ty = (tid >> 5) * 4;          // 8 row groups x 4 rows
    int tx = (tid & 31) * 4;          // 32 col groups x 4 cols
    int nCh = K >> 4;
    const int WB = 16*WS;
    float4 pw[2];
    // preload chunk 0
    #pragma unroll
    for (int i = 0; i < 2; i++) {
        int idx = tid + i*NT;
        int row = idx >> 2, k4 = (idx & 3) * 4;
        pw[i] = *(const float4*)(Wsrc + (size_t)row*ldw + k4);
    }
    #pragma unroll
    for (int i = 0; i < 2; i++) {
        int idx = tid + i*NT;
        int row = idx >> 2, k4 = (idx & 3) * 4;
        Wb[(k4+0)*WS+row]=pw[i].x; Wb[(k4+1)*WS+row]=pw[i].y;
        Wb[(k4+2)*WS+row]=pw[i].z; Wb[(k4+3)*WS+row]=pw[i].w;
    }
    __syncthreads();
    float acc[4][4] = {};
    for (int c = 0; c < nCh; c++) {
        int cur = (c & 1) * WB;
        if (c + 1 < nCh) {
            #pragma unroll
            for (int i = 0; i < 2; i++) {
                int idx = tid + i*NT;
                int row = idx >> 2, k4 = (idx & 3) * 4;
                pw[i] = *(const float4*)(Wsrc + (size_t)row*ldw + (c+1)*16 + k4);
            }
        }
        #pragma unroll
        for (int kk = 0; kk < 16; kk++) {
            int k = c*16 + kk;
            float4 bv = *(const float4*)&Wb[cur + kk*WS + tx];
            float a0 = As_[(ty+0)*asst + k];
            float a1 = As_[(ty+1)*asst + k];
            float a2 = As_[(ty+2)*asst + k];
            float a3 = As_[(ty+3)*asst + k];
            acc[0][0]+=a0*bv.x; acc[0][1]+=a0*bv.y; acc[0][2]+=a0*bv.z; acc[0][3]+=a0*bv.w;
            acc[1][0]+=a1*bv.x; acc[1][1]+=a1*bv.y; acc[1][2]+=a1*bv.z; acc[1][3]+=a1*bv.w;
            acc[2][0]+=a2*bv.x; acc[2][1]+=a2*bv.y; acc[2][2]+=a2*bv.z; acc[2][3]+=a2*bv.w;
            acc[3][0]+=a3*bv.x; acc[3][1]+=a3*bv.y; acc[3][2]+=a3*bv.z; acc[3][3]+=a3*bv.w;
        }
        if (c + 1 < nCh) {
            __syncthreads();
            int nb = ((c+1) & 1) * WB;
            #pragma unroll
            for (int i = 0; i < 2; i++) {
                int idx = tid + i*NT;
                int row = idx >> 2, k4 = (idx & 3) * 4;
                Wb[nb+(k4+0)*WS+row]=pw[i].x; Wb[nb+(k4+1)*WS+row]=pw[i].y;
                Wb[nb+(k4+2)*WS+row]=pw[i].z; Wb[nb+(k4+3)*WS+row]=pw[i].w;
            }
            __syncthreads();
        }
    }
    __syncthreads();                    // done reading Wb before caller reuses it
    #pragma unroll
    for (int i = 0; i < 4; i++) {
        #pragma unroll
        for (int j = 0; j < 4; j++) {
            float v = acc[i][j] + bias[tx+j];
            if (relu)  v = fmaxf(v, 0.f);
            if (resid) v += As_[(ty+i)*asst + (tx+j)];
            Out[(ty+i)*WS + tx+j] = v;
        }
    }
    __syncthreads();
}

__device__ void drollout(const float* __restrict__ b_sp,
                         const float* __restrict__ W_p1, const float* __restrict__ b_p1,
                         const float* __restrict__ W_p2, const float* __restrict__ b_p2,
                         const float* __restrict__ W_pl, const float* __restrict__ b_pl,
                         const float* __restrict__ cf, int cfs,
                         float* __restrict__ outp, float* sm)
{
    if (blockIdx.x >= 16) return;
    int rg = blockIdx.x, tid = threadIdx.x;
    int r0 = rg*32;
    float* X  = sm;                        // 32 x XS (x), later m1
    float* Wb = sm + 32*XS;                // 2 x 16 x WS double-buffered W chunks
    float* M1 = Wb + 2*16*WS;              // 32 x WS  (Sh, then m2)

    // stage x rows [r0, r0+32)
    for (int idx = tid; idx < 32*36; idx += NT) {
        int row = idx / 36, c4 = (idx - row*36)*4;
        *(float4*)&X[row*XS + c4] = *(const float4*)&g_x[(size_t)(r0+row)*DP + c4];
    }
    __syncthreads();

    // Sh = x @ spP^T + b_sp           -> M1
    mini_gemm(X, XS, g_spP, DP, b_sp, 0, 0, M1, DP, Wb, tid);
    // m1 = relu(Sh @ W1^T + b1) + Sh  -> X
    mini_gemm(M1, WS, W_p1, HD, b_p1, 1, 1, X, HD, Wb, tid);
    // m2 = relu(m1 @ W2^T + b2) + m1  -> M1
    mini_gemm(X, WS, W_p2, HD, b_p2, 1, 1, M1, HD, Wb, tid);

    // head: a = m2 @ W_pl^T + b_pl; kinematics; write out + g_inp
    int warp = tid >> 5, lane = tid & 31;
    for (int rr = warp; rr < 32; rr += 8) {
        const float* m2 = &M1[rr*WS];
        float a0 = 0.f, a1 = 0.f;
        #pragma unroll 4
        for (int k = lane; k < HD; k += 32) {
            float v = m2[k];
            a0 += v*W_pl[k];
            a1 += v*W_pl[HD+k];
        }
        #pragma unroll
        for (int o = 16; o; o >>= 1) {
            a0 += __shfl_xor_sync(0xffffffffu, a0, o);
            a1 += __shfl_xor_sync(0xffffffffu, a1, o);
        }
        if (lane == 0) {
            a0 += b_pl[0]; a1 += b_pl[1];
            int n = r0 + rr;
            const float* c = cf + (size_t)n*cfs;
            const float DT = 0.1f;
            float v0 = a0*DT + c[2], v1 = a1*DT + c[3];
            float p0 = a0*(DT*DT*0.5f) + v0*DT + c[0];
            float p1 = a1*(DT*DT*0.5f) + v1*DT + c[1];
            outp[n*(PLEN*4)+0] = p0; outp[n*(PLEN*4)+1] = p1;
            outp[n*(PLEN*4)+2] = v0; outp[n*(PLEN*4)+3] = v1;
            g_inp[n*4+0] = p0; g_inp[n*4+1] = p1; g_inp[n*4+2] = v0; g_inp[n*4+3] = v1;
        }
    }
    __syncthreads();
}

// ---------------- Setup phase 1 ----------------
#define RP_ROWS (NLAY*3*DD + NLAY*DD + NLAY*FFD + HD)
__device__ void dsetup(const float* W_ih, const float* W_emb, const float* b_emb,
                       const float* b_ih, const float* b_hh,
                       const float* qkv_w, const float* out_w,
                       const float* ff1_w, const float* W_sp)
{
    int gtid = blockIdx.x*NT + threadIdx.x;
    const int nthr = GRID*NT;
    for (int j = gtid; j < 4*HD; j += nthr) {
        float wc0=0.f, wc1=0.f, wc2=0.f, wc3=0.f;
        float bb = b_ih[j] + b_hh[j];
        #pragma unroll 8
        for (int e = 0; e < ED; e++) {
            float w = W_ih[j*ED + e];
            bb  += w * b_emb[e];
            wc0 += w * W_emb[e*4 + 0];
            wc1 += w * W_emb[e*4 + 1];
            wc2 += w * W_emb[e*4 + 2];
            wc3 += w * W_emb[e*4 + 3];
        }
        g_Wcomb[j*4+0]=wc0; g_Wcomb[j*4+1]=wc1; g_Wcomb[j*4+2]=wc2; g_Wcomb[j*4+3]=wc3;
        g_bcomb[j]=bb;
    }
    for (int i = gtid; i < NN*HD; i += nthr) g_c[i] = 0.f;
    for (int i = gtid; i < NN*4*HD; i += nthr) g_gates[i] = 0.f;
    for (int i = gtid; i < NN*DP; i += nthr) { g_x[i] = 0.f; g_att[i] = 0.f; }
    for (int idx = gtid; idx < RP_ROWS*DP; idx += nthr) {
        int row = idx / DP, k = idx - row*DP;
        const float* src; float* dst; int r;
        if (row < NLAY*3*DD)                         { src = qkv_w; dst = g_qkvP; r = row; }
        else if (row < NLAY*3*DD+NLAY*DD)            { src = out_w; dst = g_outP; r = row - NLAY*3*DD; }
        else if (row < NLAY*3*DD+NLAY*DD+NLAY*FFD)   { src = ff1_w; dst = g_ff1P; r = row - NLAY*3*DD - NLAY*DD; }
        else                                         { src = W_sp;  dst = g_spP;  r = row - NLAY*3*DD - NLAY*DD - NLAY*FFD; }
        dst[r*DP + k] = (k < DD) ? src[r*DD + k] : 0.f;
    }
}

// ---------------- Setup phase 2: Wf = W_hh @ spP, bspW = W_hh @ b_sp ----------------
__device__ void dsetup2(const float* W_hh, const float* b_sp)
{
    int gtid = blockIdx.x*NT + threadIdx.x;
    const int nthr = GRID*NT;
    for (int idx = gtid; idx < 4*HD*DP; idx += nthr) {
        int row = idx / DP, d = idx - row*DP;
        float s = 0.f;
        #pragma unroll 8
        for (int r = 0; r < HD; r++) s += W_hh[row*HD + r] * g_spP[r*DP + d];
        g_Wf[idx] = s;
    }
    for (int row = gtid; row < 4*HD; row += nthr) {
        float s = 0.f;
        #pragma unroll 8
        for (int r = 0; r < HD; r++) s += W_hh[row*HD + r] * b_sp[r];
        g_bspW[row] = s;
    }
}

// ---------------- Encoder stack ----------------
__device__ void dsp(const float* qkv_b, const float* out_b, const float* ff1_b,
                    const float* ff2_w, const float* ff2_b,
                    const float* ln1_s, const float* ln1_b,
                    const float* ln2_s, const float* ln2_b, float* sm)
{
    for (int j = 0; j < NLAY; j++) {
        dgemm_t<32>(g_x, g_qkvP + (size_t)j*3*DD*DP, qkv_b + j*3*DD, nullptr, g_qkv,
                    3*DD, DP, DP, 3*DD, DP, 1, 0, sm);
        gridbar();
        dattn(sm);
        gridbar();
        dgemm_t<32>(g_att, g_outP + (size_t)j*DD*DP, out_b + j*DD, nullptr, g_tmp,
                    DD, DP, DP, DP, DP, 1, 0, sm);
        gridbar();
        dln(g_tmp, 1, nullptr, ln1_s + j*DD, ln1_b + j*DD);
        gridbar();
        dgemm_t<64>(g_x, g_ff1P + (size_t)j*FFD*DP, ff1_b + j*FFD, nullptr, g_ff1,
                    FFD, DP, DP, FFD, DP, 1, 1, sm);
        gridbar();
        dgemm_t<64>(g_ff1, ff2_w + (size_t)j*DD*FFD, nullptr, nullptr, g_part,
                    DD, FFD, FFD, DP, FFD, 8, 0, sm);
        gridbar();
        dln(g_part, 8, ff2_b + j*DD, ln2_s + j*DD, ln2_b + j*DD);
        gridbar();
    }
}

// ---------------- Megakernel ----------------
__global__ void __launch_bounds__(NT, 2) mega(
    const float* Tracks, const float* W_emb, const float* b_emb,
    const float* W_ih, const float* W_hh, const float* b_ih, const float* b_hh,
    const float* qkv_w, const float* qkv_b, const float* out_w, const float* out_b,
    const float* ff1_w, const float* ff1_b, const float* ff2_w, const float* ff2_b,
    const float* ln1_s, const float* ln1_b, const float* ln2_s, const float* ln2_b,
    const float* W_sp, const float* b_sp, const float* W_p1, const float* b_p1,
    const float* W_p2, const float* b_p2, const float* W_pl, const float* b_pl,
    float* out)
{
    extern __shared__ float sm[];
    dsetup(W_ih, W_emb, b_emb, b_ih, b_hh, qkv_w, out_w, ff1_w, W_sp);
    gridbar();
    dsetup2(W_hh, b_sp);
    gridbar();

    // History: t=-1 uses Tracks[:,0,1:] with zero carry (g_gates zeroed in setup)
    for (int t = -1; t < LHIST; t++) {
        const float* ib = (t < 0) ? (Tracks + 1) : (Tracks + t*5 + 1);
        if (t >= 0) {
            // fused gates: gates = x_prev @ Wf^T + W_hh@b_sp  (== W_hh @ Sh_prev)
            dgemm_t<32>(g_x, g_Wf, g_bspW, nullptr, g_gates,
                        4*HD, DP, DP, 4*HD, DP, 1, 0, sm);
            gridbar();
        }
        dlstm_pt(ib, LHIST*5);
        gridbar();
        dsp(qkv_b, out_b, ff1_b, ff2_w, ff2_b, ln1_s, ln1_b, ln2_s, ln2_b, sm);
    }
    // Rollout: one fused phase per step (Sh -> mlp1 -> mlp2 -> head)
    for (int t = 0; t < PLEN; t++) {
        drollout(b_sp, W_p1, b_p1, W_p2, b_p2, W_pl, b_pl,
                 (t == 0) ? (Tracks + (LHIST-1)*5 + 1) : g_inp,
                 (t == 0) ? LHIST*5 : 4, out + t*4, sm);
        gridbar();
        if (t < PLEN - 1) {     // last rm_sp's carry is discarded by the scan
            dgemm_t<32>(g_x, g_Wf, g_bspW, nullptr, g_gates,
                        4*HD, DP, DP, 4*HD, DP, 1, 0, sm);
            gridbar();
            dlstm_pt(g_inp, 4);
            gridbar();
            dsp(qkv_b, out_b, ff1_b, ff2_w, ff2_b, ln1_s, ln1_b, ln2_s, ln2_b, sm);
        }
    }
}

// ---------------- Host ----------------
extern "C" void kernel_launch(void* const* d_in, const int* in_sizes, int n_in,
                              void* d_out, int out_size) {
    const float* Tracks = (const float*)d_in[0];
    const float* W_emb  = (const float*)d_in[1];
    const float* b_emb  = (const float*)d_in[2];
    const float* W_ih   = (const float*)d_in[3];
    const float* W_hh   = (const float*)d_in[4];
    const float* b_ih   = (const float*)d_in[5];
    const float* b_hh   = (const float*)d_in[6];
    const float* qkv_w  = (const float*)d_in[7];
    const float* qkv_b  = (const float*)d_in[8];
    const float* out_w  = (const float*)d_in[9];
    const float* out_b  = (const float*)d_in[10];
    const float* ff1_w  = (const float*)d_in[11];
    const float* ff1_b  = (const float*)d_in[12];
    const float* ff2_w  = (const float*)d_in[13];
    const float* ff2_b  = (const float*)d_in[14];
    const float* ln1_s  = (const float*)d_in[15];
    const float* ln1_b  = (const float*)d_in[16];
    const float* ln2_s  = (const float*)d_in[17];
    const float* ln2_b  = (const float*)d_in[18];
    const float* W_sp   = (const float*)d_in[19];
    const float* b_sp   = (const float*)d_in[20];
    const float* W_p1   = (const float*)d_in[21];
    const float* b_p1   = (const float*)d_in[22];
    const float* W_p2   = (const float*)d_in[23];
    const float* b_p2   = (const float*)d_in[24];
    const float* W_pl   = (const float*)d_in[25];
    const float* b_pl   = (const float*)d_in[26];
    float* out = (float*)d_out;

    // smem = max(attention KV: 53280B, gemm: 17408B, rollout: 52736B)
    const int SMEM = 2*ATT_SK*(int)sizeof(float);
    static int configured = 0;
    if (!configured) {
        cudaFuncSetAttribute(mega, cudaFuncAttributeMaxDynamicSharedMemorySize, SMEM);
        configured = 1;
    }

    mega<<<GRID, NT, SMEM>>>(Tracks, W_emb, b_emb, W_ih, W_hh, b_ih, b_hh,
                             qkv_w, qkv_b, out_w, out_b, ff1_w, ff1_b, ff2_w, ff2_b,
                             ln1_s, ln1_b, ln2_s, ln2_b, W_sp, b_sp,
                             W_p1, b_p1, W_p2, b_p2, W_pl, b_pl, out);
}